// round 1
// baseline (speedup 1.0000x reference)
#include <cuda_runtime.h>
#include <cstdint>

#define N_NODES 100000
#define D 64
#define E_EDGES 1600000
#define NT 3

// Scratch: per-etype aggregation of x rows and degree counts.
// 3 * 100000 * 64 * 4B = 76.8 MB, 3 * 100000 * 4B = 1.2 MB
__device__ float g_agg[NT][(size_t)N_NODES * D];
__device__ float g_deg[NT][N_NODES];

// ---------------------------------------------------------------------------
// Kernel 1: zero the scratch accumulators (vectorized).
// ---------------------------------------------------------------------------
__global__ void zero_kernel() {
    const size_t n4 = (size_t)NT * N_NODES * D / 4;
    float4* p = reinterpret_cast<float4*>(g_agg);
    const float4 z = make_float4(0.f, 0.f, 0.f, 0.f);
    for (size_t i = (size_t)blockIdx.x * blockDim.x + threadIdx.x; i < n4;
         i += (size_t)gridDim.x * blockDim.x)
        p[i] = z;
    float* d = reinterpret_cast<float*>(g_deg);
    const size_t nd = (size_t)NT * N_NODES;
    for (size_t i = (size_t)blockIdx.x * blockDim.x + threadIdx.x; i < nd;
         i += (size_t)gridDim.x * blockDim.x)
        d[i] = 0.f;
}

// ---------------------------------------------------------------------------
// Kernel 2: scatter.  16 threads per edge; each thread handles one float4
// (16 B) of the 256 B row.  Gather x[src] (L2-hot) and red.global.add.v4.f32
// into agg[etype][dst].  blockIdx.y selects the edge type.
// ---------------------------------------------------------------------------
__global__ void scatter_kernel(const float4* __restrict__ x4,
                               const int* __restrict__ s0, const int* __restrict__ d0,
                               const int* __restrict__ s1, const int* __restrict__ d1,
                               const int* __restrict__ s2, const int* __restrict__ d2) {
    const int et = blockIdx.y;
    const int* __restrict__ src = (et == 0) ? s0 : (et == 1) ? s1 : s2;
    const int* __restrict__ dst = (et == 0) ? d0 : (et == 1) ? d1 : d2;

    const long long tid = (long long)blockIdx.x * blockDim.x + threadIdx.x;
    const long long e = tid >> 4;          // edge index
    const int q = (int)(tid & 15);         // float4 slot within the row
    if (e >= E_EDGES) return;

    const int s = src[e];
    const int dd = dst[e];

    float4 v = __ldg(&x4[(size_t)s * (D / 4) + q]);

    float* out = &g_agg[et][(size_t)dd * D + q * 4];
    asm volatile("red.global.add.v4.f32 [%0], {%1, %2, %3, %4};"
                 :: "l"(out), "f"(v.x), "f"(v.y), "f"(v.z), "f"(v.w)
                 : "memory");
    if (q == 0)
        atomicAdd(&g_deg[et][dd], 1.0f);
}

// ---------------------------------------------------------------------------
// Kernel 3: finish.  One warp per node.  Per etype: normalize agg row by deg,
// multiply by W_e (in smem), add b_e.  Lane c owns output columns c and c+32.
// ---------------------------------------------------------------------------
__global__ void finish_kernel(const float* __restrict__ W0, const float* __restrict__ b0,
                              const float* __restrict__ W1, const float* __restrict__ b1,
                              const float* __restrict__ W2, const float* __restrict__ b2,
                              float* __restrict__ out) {
    __shared__ float sW[NT][D * D];   // 48 KB exactly

    for (int i = threadIdx.x; i < D * D; i += blockDim.x) {
        sW[0][i] = W0[i];
        sW[1][i] = W1[i];
        sW[2][i] = W2[i];
    }
    __syncthreads();

    const int lane = threadIdx.x & 31;
    const int warp = threadIdx.x >> 5;
    const int wpb = blockDim.x >> 5;

    for (int n = blockIdx.x * wpb + warp; n < N_NODES; n += gridDim.x * wpb) {
        float acc_lo = 0.f, acc_hi = 0.f;

        #pragma unroll
        for (int et = 0; et < NT; et++) {
            const float dg = g_deg[et][n];
            if (dg > 0.f) {
                const float inv = 1.0f / dg;
                float vlo = g_agg[et][(size_t)n * D + lane] * inv;
                float vhi = g_agg[et][(size_t)n * D + 32 + lane] * inv;

                const float* __restrict__ w = sW[et];
                #pragma unroll
                for (int k = 0; k < 32; k++) {
                    const float a = __shfl_sync(0xffffffffu, vlo, k);
                    const float c = __shfl_sync(0xffffffffu, vhi, k);
                    acc_lo += a * w[k * D + lane]        + c * w[(k + 32) * D + lane];
                    acc_hi += a * w[k * D + lane + 32]   + c * w[(k + 32) * D + lane + 32];
                }
                const float* bb = (et == 0) ? b0 : (et == 1) ? b1 : b2;
                acc_lo += __ldg(&bb[lane]);
                acc_hi += __ldg(&bb[lane + 32]);
            }
        }
        out[(size_t)n * D + lane]      = acc_lo;
        out[(size_t)n * D + 32 + lane] = acc_hi;
    }
}

// ---------------------------------------------------------------------------
// Launch.  Input order is ambiguous between dict order and signature order,
// so classify by element count (works for both):
//   6,400,000 -> x ; 4096 -> W ; 64 -> b ; 1,600,000 -> src/dst (src first).
// ---------------------------------------------------------------------------
extern "C" void kernel_launch(void* const* d_in, const int* in_sizes, int n_in,
                              void* d_out, int out_size) {
    const float* x = nullptr;
    const float* W[NT] = {nullptr, nullptr, nullptr};
    const float* b[NT] = {nullptr, nullptr, nullptr};
    const int* src[NT] = {nullptr, nullptr, nullptr};
    const int* dst[NT] = {nullptr, nullptr, nullptr};
    int wi = 0, bi = 0, ei = 0;

    for (int i = 0; i < n_in; i++) {
        const int sz = in_sizes[i];
        if (sz == N_NODES * D) {
            x = (const float*)d_in[i];
        } else if (sz == D * D) {
            if (wi < NT) W[wi++] = (const float*)d_in[i];
        } else if (sz == D) {
            if (bi < NT) b[bi++] = (const float*)d_in[i];
        } else if (sz == E_EDGES) {
            if (ei < 2 * NT) {
                if ((ei & 1) == 0) src[ei / 2] = (const int*)d_in[i];
                else               dst[ei / 2] = (const int*)d_in[i];
                ei++;
            }
        }
    }

    float* out = (float*)d_out;

    // 1) zero scratch
    zero_kernel<<<4096, 256>>>();

    // 2) scatter: E*16 threads per etype = 25.6M -> 100000 blocks of 256, y=3
    dim3 sgrid((E_EDGES * 16 + 255) / 256, NT, 1);
    scatter_kernel<<<sgrid, 256>>>((const float4*)x,
                                   src[0], dst[0], src[1], dst[1], src[2], dst[2]);

    // 3) finish: warp per node, grid-stride
    finish_kernel<<<2048, 256>>>(W[0], b[0], W[1], b[1], W[2], b[2], out);
}

// round 3
// speedup vs baseline: 1.0970x; 1.0970x over previous
#include <cuda_runtime.h>
#include <cstdint>

#define N_NODES 100000
#define D 64
#define E_EDGES 1600000
#define NT 3
#define SCAN_TILE 2048
#define NBLK ((N_NODES + SCAN_TILE - 1) / SCAN_TILE)   // 49

// ---------------- scratch (static device globals; no allocs) ----------------
__device__ int g_cnt [NT][N_NODES];     // per-etype dst histogram
__device__ int g_rp  [NT][N_NODES];     // exclusive rowptr (rp[N] implied = E)
__device__ int g_off [NT][N_NODES];     // running placement cursors
__device__ int g_part[NT][NBLK];        // scan block partials
__device__ int g_srcs[NT][E_EDGES];     // src ids grouped by dst (CSR payload)

// ---------------------------------------------------------------------------
// 0) zero histograms
// ---------------------------------------------------------------------------
__global__ void zero_cnt_kernel() {
    int* p = &g_cnt[0][0];
    const int n = NT * N_NODES;
    for (int i = blockIdx.x * blockDim.x + threadIdx.x; i < n;
         i += gridDim.x * blockDim.x)
        p[i] = 0;
}

// ---------------------------------------------------------------------------
// 1) histogram of dst per etype
// ---------------------------------------------------------------------------
__global__ void hist_kernel(const int* __restrict__ d0,
                            const int* __restrict__ d1,
                            const int* __restrict__ d2) {
    const int et = blockIdx.y;
    const int* __restrict__ dst = (et == 0) ? d0 : (et == 1) ? d1 : d2;
    for (int e = blockIdx.x * blockDim.x + threadIdx.x; e < E_EDGES;
         e += gridDim.x * blockDim.x)
        atomicAdd(&g_cnt[et][dst[e]], 1);
}

// ---------------------------------------------------------------------------
// 2a) block-level exclusive scan (tile = 2048, 1024 threads, 2 elems/thread)
// ---------------------------------------------------------------------------
__global__ void scan1_kernel() {
    __shared__ int sh[1024];
    const int et = blockIdx.y;
    const int base = blockIdx.x * SCAN_TILE;
    const int t = threadIdx.x;
    const int i0 = base + 2 * t, i1 = i0 + 1;

    int v0 = (i0 < N_NODES) ? g_cnt[et][i0] : 0;
    int v1 = (i1 < N_NODES) ? g_cnt[et][i1] : 0;
    const int tot = v0 + v1;
    sh[t] = tot;
    __syncthreads();
    for (int off = 1; off < 1024; off <<= 1) {
        int add = (t >= off) ? sh[t - off] : 0;
        __syncthreads();
        sh[t] += add;
        __syncthreads();
    }
    const int excl = sh[t] - tot;
    if (i0 < N_NODES) g_rp[et][i0] = excl;
    if (i1 < N_NODES) g_rp[et][i1] = excl + v0;
    if (t == 1023) g_part[et][blockIdx.x] = sh[1023];
}

// ---------------------------------------------------------------------------
// 2b) scan the 49 partials per etype (trivial serial)
// ---------------------------------------------------------------------------
__global__ void scan2_kernel() {
    const int et = threadIdx.x;
    if (et < NT) {
        int acc = 0;
        for (int b = 0; b < NBLK; b++) {
            const int v = g_part[et][b];
            g_part[et][b] = acc;
            acc += v;
        }
    }
}

// ---------------------------------------------------------------------------
// 2c) add block offsets -> final rowptr; seed placement cursors
// ---------------------------------------------------------------------------
__global__ void scan3_kernel() {
    const int et = blockIdx.y;
    for (int i = blockIdx.x * blockDim.x + threadIdx.x; i < N_NODES;
         i += gridDim.x * blockDim.x) {
        const int v = g_rp[et][i] + g_part[et][i / SCAN_TILE];
        g_rp[et][i] = v;
        g_off[et][i] = v;
    }
}

// ---------------------------------------------------------------------------
// 3) placement: bucket src ids by dst
// ---------------------------------------------------------------------------
__global__ void place_kernel(const int* __restrict__ s0, const int* __restrict__ d0,
                             const int* __restrict__ s1, const int* __restrict__ d1,
                             const int* __restrict__ s2, const int* __restrict__ d2) {
    const int et = blockIdx.y;
    const int* __restrict__ src = (et == 0) ? s0 : (et == 1) ? s1 : s2;
    const int* __restrict__ dst = (et == 0) ? d0 : (et == 1) ? d1 : d2;
    for (int e = blockIdx.x * blockDim.x + threadIdx.x; e < E_EDGES;
         e += gridDim.x * blockDim.x) {
        const int p = atomicAdd(&g_off[et][dst[e]], 1);
        g_srcs[et][p] = src[e];
    }
}

// ---------------------------------------------------------------------------
// 4) fused gather + mean + GEMM + bias.  One warp per node.
//    Lane c owns output columns c and c+32.
// ---------------------------------------------------------------------------
__global__ void fused_kernel(const float* __restrict__ x,
                             const float* __restrict__ W0, const float* __restrict__ b0,
                             const float* __restrict__ W1, const float* __restrict__ b1,
                             const float* __restrict__ W2, const float* __restrict__ b2,
                             float* __restrict__ out) {
    __shared__ float sW[NT][D * D];   // 48 KB
    for (int i = threadIdx.x; i < D * D; i += blockDim.x) {
        sW[0][i] = W0[i];
        sW[1][i] = W1[i];
        sW[2][i] = W2[i];
    }
    __syncthreads();

    const int lane = threadIdx.x & 31;
    const int warp = threadIdx.x >> 5;
    const int wpb = blockDim.x >> 5;

    for (int n = blockIdx.x * wpb + warp; n < N_NODES; n += gridDim.x * wpb) {
        float acc_lo = 0.f, acc_hi = 0.f;

        #pragma unroll
        for (int et = 0; et < NT; et++) {
            const int beg = g_rp[et][n];
            const int end = (n == N_NODES - 1) ? E_EDGES : g_rp[et][n + 1];
            const int deg = end - beg;
            if (deg > 0) {
                float vlo = 0.f, vhi = 0.f;
                for (int b = beg; b < end; b += 32) {
                    const int cnt = min(32, end - b);
                    const int sv = (lane < cnt) ? g_srcs[et][b + lane] : 0;
                    #pragma unroll 4
                    for (int j = 0; j < cnt; j++) {
                        const int s = __shfl_sync(0xffffffffu, sv, j);
                        vlo += __ldg(&x[(size_t)s * D + lane]);
                        vhi += __ldg(&x[(size_t)s * D + 32 + lane]);
                    }
                }
                const float inv = 1.0f / (float)deg;
                vlo *= inv;
                vhi *= inv;

                const float* __restrict__ w = sW[et];
                #pragma unroll
                for (int k = 0; k < 32; k++) {
                    const float a = __shfl_sync(0xffffffffu, vlo, k);
                    const float c = __shfl_sync(0xffffffffu, vhi, k);
                    acc_lo += a * w[k * D + lane]      + c * w[(k + 32) * D + lane];
                    acc_hi += a * w[k * D + lane + 32] + c * w[(k + 32) * D + lane + 32];
                }
                const float* bb = (et == 0) ? b0 : (et == 1) ? b1 : b2;
                acc_lo += __ldg(&bb[lane]);
                acc_hi += __ldg(&bb[lane + 32]);
            }
        }
        out[(size_t)n * D + lane]      = acc_lo;
        out[(size_t)n * D + 32 + lane] = acc_hi;
    }
}

// ---------------------------------------------------------------------------
// Launch.  Inputs classified by element count (robust to ordering):
//   6,400,000 -> x ; 4096 -> W ; 64 -> b ; 1,600,000 -> src/dst (src first).
// ---------------------------------------------------------------------------
extern "C" void kernel_launch(void* const* d_in, const int* in_sizes, int n_in,
                              void* d_out, int out_size) {
    const float* x = nullptr;
    const float* W[NT] = {};
    const float* b[NT] = {};
    const int* src[NT] = {};
    const int* dst[NT] = {};
    int wi = 0, bi = 0, ei = 0;

    for (int i = 0; i < n_in; i++) {
        const int sz = in_sizes[i];
        if (sz == N_NODES * D) {
            x = (const float*)d_in[i];
        } else if (sz == D * D) {
            if (wi < NT) W[wi++] = (const float*)d_in[i];
        } else if (sz == D) {
            if (bi < NT) b[bi++] = (const float*)d_in[i];
        } else if (sz == E_EDGES) {
            if (ei < 2 * NT) {
                if ((ei & 1) == 0) src[ei / 2] = (const int*)d_in[i];
                else               dst[ei / 2] = (const int*)d_in[i];
                ei++;
            }
        }
    }

    float* out = (float*)d_out;

    zero_cnt_kernel<<<512, 256>>>();

    dim3 egrid((E_EDGES + 255) / 256, NT, 1);
    hist_kernel<<<egrid, 256>>>(dst[0], dst[1], dst[2]);

    dim3 sgrid(NBLK, NT, 1);
    scan1_kernel<<<sgrid, 1024>>>();
    scan2_kernel<<<1, 32>>>();
    dim3 s3grid((N_NODES + 255) / 256, NT, 1);
    scan3_kernel<<<s3grid, 256>>>();

    place_kernel<<<egrid, 256>>>(src[0], dst[0], src[1], dst[1], src[2], dst[2]);

    // 8 warps/block, warp per node
    fused_kernel<<<(N_NODES + 7) / 8, 256>>>(x, W[0], b[0], W[1], b[1], W[2], b[2], out);
}